// round 16
// baseline (speedup 1.0000x reference)
#include <cuda_runtime.h>
#include <cuda_fp16.h>
#include <math.h>

#define Nn   50000
#define Ee   800000
#define EPt  850000   // E + N self loops
#define Gg   64
#define NBLK 49       // ceil(Nn/1024)

// ---------------- scratch ----------------
__device__ __align__(16) __half g_h1  [(size_t)Nn*128];
__device__ __align__(16) __half g_out1[(size_t)Nn*128];
__device__ __align__(16) __half g_h2  [(size_t)Nn*64];
__device__ __align__(16) float  g_asrc1[Nn*4];
__device__ __align__(16) float  g_adst1[Nn*4];
__device__ __align__(16) float  g_asrc2[Nn];
__device__ __align__(16) float  g_adst2[Nn];
__device__ __align__(16) int    g_ssrc [EPt];
__device__ __align__(16) float  g_sae1 [(size_t)EPt*4];
__device__ __align__(16) float  g_sae2 [EPt];
__device__ __align__(16) int    g_deg  [Nn];
__device__ __align__(16) int    g_off  [Nn+1];
__device__ __align__(16) int    g_cur  [Nn];
__device__ __align__(16) int    g_bsum [NBLK];
__device__ __align__(16) int    g_boff [NBLK];
__device__ __align__(16) float  g_sum_ea[16];
__device__ __align__(16) float  g_v1[64];
__device__ __align__(16) float  g_v2[16];
__device__ __align__(16) float  g_pool[Gg*64];
__device__ __align__(16) int    g_cnt [Gg];

__device__ __forceinline__ float lrelu(float x){ return x > 0.f ? x : 0.2f*x; }

// ---------------- 1. init ----------------
__global__ void k_init(const float* __restrict__ We1, const float* __restrict__ ae1,
                       const float* __restrict__ We2, const float* __restrict__ ae2){
    int i = blockIdx.x*blockDim.x + threadIdx.x;
    if(i < Nn){ g_deg[i]=1; g_cur[i]=0; }
    if(i < 16) g_sum_ea[i]=0.f;
    if(i < Gg*64) g_pool[i]=0.f;
    if(i < Gg) g_cnt[i]=0;
    if(blockIdx.x == 0){
        int t = threadIdx.x;
        if(t < 64){
            int h = t >> 4, d = t & 15;
            float s = 0.f;
            for(int c=0;c<32;c++) s += We1[d*128 + h*32 + c] * ae1[h*32 + c];
            g_v1[h*16 + d] = s;
        }
        if(t < 16){
            float s = 0.f;
            for(int c=0;c<64;c++) s += We2[t*64 + c] * ae2[c];
            g_v2[t] = s;
        }
    }
}

// ---------------- 2. hist only ----------------
__global__ void k_hist(const int* __restrict__ ei){
    int e = blockIdx.x*blockDim.x + threadIdx.x;
    if(e < Ee) atomicAdd(&g_deg[__ldg(&ei[Ee + e])], 1);
}

// ---------------- 3. scan ----------------
__global__ void k_scanA(){
    __shared__ int wsum[8], wexc[8];
    int t = threadIdx.x, blk = blockIdx.x;
    int base = blk*1024 + t*4;
    int v0 = (base+0<Nn)?g_deg[base+0]:0;
    int v1 = (base+1<Nn)?g_deg[base+1]:0;
    int v2 = (base+2<Nn)?g_deg[base+2]:0;
    int v3 = (base+3<Nn)?g_deg[base+3]:0;
    int s = v0+v1+v2+v3;
    int lane = t&31, w = t>>5;
    int ps = s;
#pragma unroll
    for(int off=1; off<32; off<<=1){
        int n = __shfl_up_sync(0xffffffffu, ps, off);
        if(lane>=off) ps += n;
    }
    if(lane==31) wsum[w] = ps;
    __syncthreads();
    if(t==0){
        int r=0;
#pragma unroll
        for(int k=0;k<8;k++){ wexc[k]=r; r+=wsum[k]; }
        g_bsum[blk]=r;
    }
    __syncthreads();
    int run = wexc[w] + ps - s;
    if(base+0<Nn) g_off[base+0]=run; run+=v0;
    if(base+1<Nn) g_off[base+1]=run; run+=v1;
    if(base+2<Nn) g_off[base+2]=run; run+=v2;
    if(base+3<Nn) g_off[base+3]=run;
}
__global__ void k_scanB(){
    if(threadIdx.x==0){
        int r=0;
        for(int b=0;b<NBLK;b++){ g_boff[b]=r; r+=g_bsum[b]; }
        g_off[Nn]=EPt;
    }
}
__global__ void k_scanC(){
    int blk = blockIdx.x;
    if(blk==0) return;
    int add = g_boff[blk];
    int base = blk*1024 + threadIdx.x*4;
#pragma unroll
    for(int j=0;j<4;j++)
        if(base+j < Nn) g_off[base+j] += add;
}

// ---------------- 4. scatter: dots from ea + sum_ea; slot 0 reserved ----------------
__global__ __launch_bounds__(256) void k_scatter(const int* __restrict__ ei,
                                                 const float* __restrict__ ea){
    __shared__ float sv1[64], sv2[16], ssum[16];
    int t = threadIdx.x;
    if(t < 64) sv1[t] = g_v1[t];
    if(t < 16){ sv2[t] = g_v2[t]; ssum[t] = 0.f; }
    __syncthreads();
    int e = blockIdx.x*blockDim.x + t;
    float r[16];
#pragma unroll
    for(int i=0;i<16;i++) r[i]=0.f;
    if(e < Ee){
        int s = __ldg(&ei[e]), d = __ldg(&ei[Ee + e]);
        const float4* rp = (const float4*)(ea + (size_t)e*16);
        ((float4*)r)[0]=__ldg(rp);   ((float4*)r)[1]=__ldg(rp+1);
        ((float4*)r)[2]=__ldg(rp+2); ((float4*)r)[3]=__ldg(rp+3);
        float ae[4];
#pragma unroll
        for(int h=0;h<4;h++){
            float a=0.f;
#pragma unroll
            for(int i=0;i<16;i++) a += sv1[h*16+i]*r[i];
            ae[h]=a;
        }
        float a2=0.f;
#pragma unroll
        for(int i=0;i<16;i++) a2 += sv2[i]*r[i];
        int pos = g_off[d] + 1 + atomicAdd(&g_cur[d], 1);
        g_ssrc[pos] = s;
        *(float4*)&g_sae1[(size_t)pos*4] = make_float4(ae[0],ae[1],ae[2],ae[3]);
        g_sae2[pos] = a2;
    }
#pragma unroll
    for(int off=16; off; off>>=1)
#pragma unroll
        for(int i=0;i<16;i++) r[i] += __shfl_xor_sync(0xffffffffu, r[i], off);
    if((t & 31)==0)
#pragma unroll
        for(int i=0;i<16;i++) atomicAdd(&ssum[i], r[i]);
    __syncthreads();
    if(t < 16) atomicAdd(&g_sum_ea[t], ssum[t]);
}

// ---------------- 5. self-loop fill ----------------
__global__ void k_selfloop(){
    __shared__ float slae1[4];
    __shared__ float slae2;
    int t = threadIdx.x;
    if(t < 4){
        float s = 0.f;
        for(int d=0;d<16;d++) s += (g_sum_ea[d]*(1.0f/(float)Ee))*g_v1[t*16+d];
        slae1[t] = s;
    }
    if(t == 4){
        float s = 0.f;
        for(int d=0;d<16;d++) s += (g_sum_ea[d]*(1.0f/(float)Ee))*g_v2[d];
        slae2 = s;
    }
    __syncthreads();
    int d = blockIdx.x*blockDim.x + t;
    if(d >= Nn) return;
    int pos = g_off[d];
    g_ssrc[pos] = d;
    *(float4*)&g_sae1[(size_t)pos*4] = make_float4(slae1[0],slae1[1],slae1[2],slae1[3]);
    g_sae2[pos] = slae2;
}

// ---------------- 6. GEMM: 64xNC block, 128 threads, 8x(NC/16) register tile ----------------
template<int NC, bool ELU, typename TA>
__global__ __launch_bounds__(128) void k_gemm(const TA* __restrict__ A,
                                              const float* __restrict__ W,
                                              const float* __restrict__ abias,
                                              const float* __restrict__ atts,
                                              const float* __restrict__ attd,
                                              __half* __restrict__ C,
                                              float* __restrict__ oasrc,
                                              float* __restrict__ oadst, int M){
    constexpr int CPT = NC/16;
    constexpr int AST = 68;
    __shared__ float AsT[32*AST];
    __shared__ float Ws[32*NC];
    __shared__ float as_s[NC], ad_s[NC];
    const int t  = threadIdx.x;
    const int tr = t >> 4, tc = t & 15;
    const int r0 = blockIdx.x * 64;
    if(t < NC){ as_s[t]=__ldg(&atts[t]); ad_s[t]=__ldg(&attd[t]); }
    float acc[8][CPT];
#pragma unroll
    for(int i=0;i<8;i++)
#pragma unroll
        for(int j=0;j<CPT;j++) acc[i][j]=0.f;

    for(int kc=0; kc<128; kc+=32){
        if constexpr (!ELU){
#pragma unroll
            for(int i=0;i<4;i++){
                int idx = t + i*128; int r = idx>>3; int c4 = idx&7;
                float4 v = make_float4(0.f,0.f,0.f,0.f);
                if(r0 + r < M) v = __ldg((const float4*)&((const float*)A)[(size_t)(r0+r)*128 + kc + c4*4]);
                AsT[(c4*4+0)*AST + r] = v.x;
                AsT[(c4*4+1)*AST + r] = v.y;
                AsT[(c4*4+2)*AST + r] = v.z;
                AsT[(c4*4+3)*AST + r] = v.w;
            }
        } else {
#pragma unroll
            for(int i=0;i<2;i++){
                int idx = t + i*128; int r = idx>>2; int c8 = (idx&3)*8;
                float f[8] = {0,0,0,0,0,0,0,0};
                if(r0 + r < M){
                    uint4 u = __ldg((const uint4*)&((const __half*)A)[(size_t)(r0+r)*128 + kc + c8]);
                    float2 a0=__half22float2(*(__half2*)&u.x), a1=__half22float2(*(__half2*)&u.y);
                    float2 a2=__half22float2(*(__half2*)&u.z), a3=__half22float2(*(__half2*)&u.w);
                    f[0]=a0.x; f[1]=a0.y; f[2]=a1.x; f[3]=a1.y;
                    f[4]=a2.x; f[5]=a2.y; f[6]=a3.x; f[7]=a3.y;
                    float4 b0 = __ldg((const float4*)&abias[kc+c8]);
                    float4 b1 = __ldg((const float4*)&abias[kc+c8+4]);
                    f[0]+=b0.x; f[1]+=b0.y; f[2]+=b0.z; f[3]+=b0.w;
                    f[4]+=b1.x; f[5]+=b1.y; f[6]+=b1.z; f[7]+=b1.w;
#pragma unroll
                    for(int j=0;j<8;j++) f[j] = f[j]>0.f ? f[j] : expm1f(f[j]);
                }
#pragma unroll
                for(int j=0;j<8;j++) AsT[(c8+j)*AST + r] = f[j];
            }
        }
#pragma unroll
        for(int f=t; f < 32*NC/4; f += 128){
            int k = f/(NC/4); int c = f%(NC/4);
            *(float4*)&Ws[k*NC + c*4] = __ldg((const float4*)&W[(size_t)(kc+k)*NC + c*4]);
        }
        __syncthreads();
#pragma unroll 4
        for(int kk=0; kk<32; kk++){
            float4 a0 = *(const float4*)&AsT[kk*AST + tr*8];
            float4 a1 = *(const float4*)&AsT[kk*AST + tr*8 + 4];
            float av[8] = {a0.x,a0.y,a0.z,a0.w,a1.x,a1.y,a1.z,a1.w};
            float4 b0 = *(const float4*)&Ws[kk*NC + tc*CPT];
#pragma unroll
            for(int i=0;i<8;i++){
                acc[i][0]+=av[i]*b0.x; acc[i][1]+=av[i]*b0.y;
                acc[i][2]+=av[i]*b0.z; acc[i][3]+=av[i]*b0.w;
            }
            if constexpr (CPT == 8){
                float4 b1 = *(const float4*)&Ws[kk*NC + tc*CPT + 4];
#pragma unroll
                for(int i=0;i<8;i++){
                    acc[i][4]+=av[i]*b1.x; acc[i][5]+=av[i]*b1.y;
                    acc[i][6]+=av[i]*b1.z; acc[i][7]+=av[i]*b1.w;
                }
            }
        }
        __syncthreads();
    }
#pragma unroll
    for(int i=0;i<8;i++){
        int row = r0 + tr*8 + i;
        float ps=0.f, pd=0.f;
#pragma unroll
        for(int j=0;j<CPT;j++){
            float a = acc[i][j];
            ps += a*as_s[tc*CPT+j]; pd += a*ad_s[tc*CPT+j];
        }
        if constexpr (NC == 128){
            ps += __shfl_xor_sync(0xffffffffu, ps, 1); pd += __shfl_xor_sync(0xffffffffu, pd, 1);
            ps += __shfl_xor_sync(0xffffffffu, ps, 2); pd += __shfl_xor_sync(0xffffffffu, pd, 2);
            if((tc&3)==0 && row<M){ oasrc[row*4+(tc>>2)]=ps; oadst[row*4+(tc>>2)]=pd; }
        } else {
            ps += __shfl_xor_sync(0xffffffffu, ps, 1); pd += __shfl_xor_sync(0xffffffffu, pd, 1);
            ps += __shfl_xor_sync(0xffffffffu, ps, 2); pd += __shfl_xor_sync(0xffffffffu, pd, 2);
            ps += __shfl_xor_sync(0xffffffffu, ps, 4); pd += __shfl_xor_sync(0xffffffffu, pd, 4);
            ps += __shfl_xor_sync(0xffffffffu, ps, 8); pd += __shfl_xor_sync(0xffffffffu, pd, 8);
            if(tc==0 && row<M){ oasrc[row]=ps; oadst[row]=pd; }
        }
        if(row < M){
            __half2 hh[CPT/2];
#pragma unroll
            for(int j=0;j<CPT/2;j++)
                hh[j] = __float22half2_rn(make_float2(acc[i][2*j], acc[i][2*j+1]));
            if constexpr (CPT == 8)
                *(uint4*)&C[(size_t)row*NC + tc*CPT] = *(uint4*)hh;
            else
                *(uint2*)&C[(size_t)row*NC + tc*CPT] = *(uint2*)hh;
        }
    }
}

// ---------------- 7. fused layer-1: batch-16 cooperative, 2 nodes/warp ----------------
#define COMB8(a, u) { \
    float2 fa=__half22float2(*(__half2*)&(u).x), fb=__half22float2(*(__half2*)&(u).y); \
    float2 fc=__half22float2(*(__half2*)&(u).z), fd=__half22float2(*(__half2*)&(u).w); \
    if((a) <= m){ float w_=__expf((a)-m); sden+=w_; \
        acc[0]+=fa.x*w_; acc[1]+=fa.y*w_; acc[2]+=fb.x*w_; acc[3]+=fb.y*w_; \
        acc[4]+=fc.x*w_; acc[5]+=fc.y*w_; acc[6]+=fd.x*w_; acc[7]+=fd.y*w_; } \
    else { float sc=__expf(m-(a)); sden=sden*sc+1.f; \
        acc[0]=acc[0]*sc+fa.x; acc[1]=acc[1]*sc+fa.y; acc[2]=acc[2]*sc+fb.x; acc[3]=acc[3]*sc+fb.y; \
        acc[4]=acc[4]*sc+fc.x; acc[5]=acc[5]*sc+fc.y; acc[6]=acc[6]*sc+fd.x; acc[7]=acc[7]*sc+fd.y; m=(a);} }

__global__ __launch_bounds__(256) void k_layer1(){
    int lane = threadIdx.x & 31;
    int warp = (blockIdx.x*blockDim.x + threadIdx.x) >> 5;
    int side = lane >> 4, sl = lane & 15;
    int d = warp*2 + side;
    if(d >= Nn) return;                 // Nn even: both halves valid together
    int beg = g_off[d], end = g_off[d+1];
    int h = sl >> 2;
    float4 adst4 = *(const float4*)&g_adst1[d*4];
    float m = -1e30f, sden = 0.f;
    float acc[8] = {0.f,0.f,0.f,0.f,0.f,0.f,0.f,0.f};
    for(int base = beg; base < end; base += 16){
        // cooperative: lane sl owns edge base+sl
        int j = base + sl;
        int srcj = 0;
        float4 al4 = make_float4(-INFINITY,-INFINITY,-INFINITY,-INFINITY);
        if(j < end){
            srcj = __ldg(&g_ssrc[j]);
            float4 sae = __ldg((const float4*)&g_sae1[(size_t)j*4]);
            float4 asr = __ldg((const float4*)&g_asrc1[srcj*4]);
            al4.x = lrelu(asr.x + adst4.x + sae.x);
            al4.y = lrelu(asr.y + adst4.y + sae.y);
            al4.z = lrelu(asr.z + adst4.z + sae.z);
            al4.w = lrelu(asr.w + adst4.w + sae.w);
        }
        int cnt = min(16, end - base);
        for(int k = 0; k < cnt; k += 4){
            int s_[4]; float a_[4]; uint4 hv[4];
#pragma unroll
            for(int u=0;u<4;u++){
                int srcl = side*16 + k + u;
                s_[u] = __shfl_sync(0xffffffffu, srcj, srcl);
                float ax = __shfl_sync(0xffffffffu, al4.x, srcl);
                float ay = __shfl_sync(0xffffffffu, al4.y, srcl);
                float az = __shfl_sync(0xffffffffu, al4.z, srcl);
                float aw = __shfl_sync(0xffffffffu, al4.w, srcl);
                a_[u] = (h==0)?ax:(h==1)?ay:(h==2)?az:aw;
            }
#pragma unroll
            for(int u=0;u<4;u++)
                hv[u] = __ldg((const uint4*)&g_h1[(size_t)s_[u]*128 + sl*8]);
#pragma unroll
            for(int u=0;u<4;u++){
                COMB8(a_[u], hv[u]);
            }
        }
    }
    float inv = 1.f/sden;
    __half2 o[4];
#pragma unroll
    for(int j=0;j<4;j++)
        o[j] = __float22half2_rn(make_float2(acc[2*j]*inv, acc[2*j+1]*inv));
    *(uint4*)&g_out1[(size_t)d*128 + sl*8] = *(uint4*)o;
}

// ---------------- 8. fused layer-2 + pool: batch-16 cooperative, 2 nodes/warp ----------------
#define COMB4(a, u) { \
    float2 fa=__half22float2(*(__half2*)&(u).x), fb=__half22float2(*(__half2*)&(u).y); \
    if((a) <= m){ float w_=__expf((a)-m); sden+=w_; \
        acc[0]+=fa.x*w_; acc[1]+=fa.y*w_; acc[2]+=fb.x*w_; acc[3]+=fb.y*w_; } \
    else { float sc=__expf(m-(a)); sden=sden*sc+1.f; \
        acc[0]=acc[0]*sc+fa.x; acc[1]=acc[1]*sc+fa.y; acc[2]=acc[2]*sc+fb.x; acc[3]=acc[3]*sc+fb.y; m=(a);} }

__global__ __launch_bounds__(256) void k_layer2(const int* __restrict__ batch){
    int lane = threadIdx.x & 31;
    int warp = (blockIdx.x*blockDim.x + threadIdx.x) >> 5;
    int side = lane >> 4, sl = lane & 15;
    int d = warp*2 + side;
    if(d >= Nn) return;
    int beg = g_off[d], end = g_off[d+1];
    float adst = __ldg(&g_adst2[d]);
    float m = -1e30f, sden = 0.f;
    float acc[4] = {0.f,0.f,0.f,0.f};
    for(int base = beg; base < end; base += 16){
        int j = base + sl;
        int srcj = 0;
        float aj = -INFINITY;
        if(j < end){
            srcj = __ldg(&g_ssrc[j]);
            aj = lrelu(__ldg(&g_asrc2[srcj]) + adst + __ldg(&g_sae2[j]));
        }
        int cnt = min(16, end - base);
        for(int k = 0; k < cnt; k += 4){
            int s_[4]; float a_[4]; uint2 hv[4];
#pragma unroll
            for(int u=0;u<4;u++){
                int srcl = side*16 + k + u;
                s_[u] = __shfl_sync(0xffffffffu, srcj, srcl);
                a_[u] = __shfl_sync(0xffffffffu, aj, srcl);
            }
#pragma unroll
            for(int u=0;u<4;u++)
                hv[u] = __ldg((const uint2*)&g_h2[(size_t)s_[u]*64 + sl*4]);
#pragma unroll
            for(int u=0;u<4;u++){
                COMB4(a_[u], hv[u]);
            }
        }
    }
    float inv = 1.f/sden;
    int g = __ldg(&batch[d]);
    atomicAdd((float4*)&g_pool[g*64 + sl*4],
              make_float4(acc[0]*inv, acc[1]*inv, acc[2]*inv, acc[3]*inv));
    if(sl==0) atomicAdd(&g_cnt[g], 1);
}

// ---------------- 9. final ----------------
__global__ void k_final(float* __restrict__ out, const float* __restrict__ b2){
    int i = blockIdx.x*blockDim.x + threadIdx.x;
    if(i >= Gg*64) return;
    out[i] = g_pool[i] / fmaxf((float)g_cnt[i >> 6], 1.0f) + __ldg(&b2[i & 63]);
}

// ---------------- host launcher ----------------
extern "C" void kernel_launch(void* const* d_in, const int* in_sizes, int n_in,
                              void* d_out, int out_size){
    (void)in_sizes; (void)n_in; (void)out_size;
    const float* x     = (const float*)d_in[0];
    const int*   ei    = (const int*)d_in[1];
    const float* ea    = (const float*)d_in[2];
    const int*   batch = (const int*)d_in[3];
    const float* W1    = (const float*)d_in[4];
    const float* as1   = (const float*)d_in[5];
    const float* ad1   = (const float*)d_in[6];
    const float* We1   = (const float*)d_in[7];
    const float* ae1   = (const float*)d_in[8];
    const float* b1    = (const float*)d_in[9];
    const float* W2    = (const float*)d_in[10];
    const float* as2   = (const float*)d_in[11];
    const float* ad2   = (const float*)d_in[12];
    const float* We2   = (const float*)d_in[13];
    const float* ae2   = (const float*)d_in[14];
    const float* b2    = (const float*)d_in[15];
    float*       out   = (float*)d_out;

    void *p_h1,*p_out1,*p_h2,*p_asrc1,*p_adst1,*p_asrc2,*p_adst2;
    cudaGetSymbolAddress(&p_h1,   g_h1);
    cudaGetSymbolAddress(&p_out1, g_out1);
    cudaGetSymbolAddress(&p_h2,   g_h2);
    cudaGetSymbolAddress(&p_asrc1, g_asrc1);
    cudaGetSymbolAddress(&p_adst1, g_adst1);
    cudaGetSymbolAddress(&p_asrc2, g_asrc2);
    cudaGetSymbolAddress(&p_adst2, g_adst2);

    cudaStream_t s2;
    cudaEvent_t evFork, evJoin;
    cudaStreamCreateWithFlags(&s2, cudaStreamNonBlocking);
    cudaEventCreateWithFlags(&evFork, cudaEventDisableTiming);
    cudaEventCreateWithFlags(&evJoin, cudaEventDisableTiming);

    cudaEventRecord(evFork, 0);

    k_init<<<(Nn+255)/256, 256>>>(We1, ae1, We2, ae2);   // #1
    k_hist<<<(Ee+255)/256, 256>>>(ei);                   // #2
    k_scanA<<<NBLK, 256>>>();                            // #3

    cudaStreamWaitEvent(s2, evFork, 0);
    k_gemm<128,false,float><<<(Nn+63)/64, 128, 0, s2>>>(x, W1, nullptr, as1, ad1,
                        (__half*)p_h1, (float*)p_asrc1, (float*)p_adst1, Nn);  // #4 (ncu target)
    cudaEventRecord(evJoin, s2);

    k_scanB<<<1, 32>>>();                                // #5
    k_scanC<<<NBLK, 256>>>();                            // #6
    k_scatter<<<(Ee+255)/256, 256>>>(ei, ea);            // #7
    k_selfloop<<<(Nn+255)/256, 256>>>();                 // #8

    cudaStreamWaitEvent(0, evJoin, 0);
    k_layer1<<<(Nn/2*32+255)/256, 256>>>();              // #9

    k_gemm<64,true,__half><<<(Nn+63)/64, 128>>>((const __half*)p_out1, W2, b1, as2, ad2,
                        (__half*)p_h2, (float*)p_asrc2, (float*)p_adst2, Nn);  // #10
    k_layer2<<<(Nn/2*32+255)/256, 256>>>(batch);         // #11

    k_final<<<(Gg*64+255)/256, 256>>>(out, b2);          // #12
}

// round 17
// speedup vs baseline: 1.0648x; 1.0648x over previous
#include <cuda_runtime.h>
#include <cuda_fp16.h>
#include <math.h>

#define Nn   50000
#define Ee   800000
#define EPt  850000   // E + N self loops
#define Gg   64
#define NBLK 49       // ceil(Nn/1024)

// ---------------- scratch ----------------
__device__ __align__(16) __half g_h1  [(size_t)Nn*128];
__device__ __align__(16) __half g_out1[(size_t)Nn*128];
__device__ __align__(16) __half g_h2  [(size_t)Nn*64];
__device__ __align__(16) float  g_asrc1[Nn*4];
__device__ __align__(16) float  g_adst1[Nn*4];
__device__ __align__(16) float  g_asrc2[Nn];
__device__ __align__(16) float  g_adst2[Nn];
__device__ __align__(16) int    g_ssrc [EPt];
__device__ __align__(16) float  g_sae1 [(size_t)EPt*4];
__device__ __align__(16) float  g_sae2 [EPt];
__device__ __align__(16) int    g_deg  [Nn];
__device__ __align__(16) int    g_off  [Nn+1];
__device__ __align__(16) int    g_cur  [Nn];
__device__ __align__(16) int    g_bsum [NBLK];
__device__ __align__(16) int    g_boff [NBLK];
__device__ __align__(16) float  g_sum_ea[16];
__device__ __align__(16) float  g_v1[64];
__device__ __align__(16) float  g_v2[16];
__device__ __align__(16) float  g_pool[Gg*64];
__device__ __align__(16) int    g_cnt [Gg];

__device__ __forceinline__ float lrelu(float x){ return x > 0.f ? x : 0.2f*x; }

// ---------------- 1. init ----------------
__global__ void k_init(const float* __restrict__ We1, const float* __restrict__ ae1,
                       const float* __restrict__ We2, const float* __restrict__ ae2){
    int i = blockIdx.x*blockDim.x + threadIdx.x;
    if(i < Nn){ g_deg[i]=1; g_cur[i]=0; }
    if(i < 16) g_sum_ea[i]=0.f;
    if(i < Gg*64) g_pool[i]=0.f;
    if(i < Gg) g_cnt[i]=0;
    if(blockIdx.x == 0){
        int t = threadIdx.x;
        if(t < 64){
            int h = t >> 4, d = t & 15;
            float s = 0.f;
            for(int c=0;c<32;c++) s += We1[d*128 + h*32 + c] * ae1[h*32 + c];
            g_v1[h*16 + d] = s;
        }
        if(t < 16){
            float s = 0.f;
            for(int c=0;c<64;c++) s += We2[t*64 + c] * ae2[c];
            g_v2[t] = s;
        }
    }
}

// ---------------- 2. hist only ----------------
__global__ void k_hist(const int* __restrict__ ei){
    int e = blockIdx.x*blockDim.x + threadIdx.x;
    if(e < Ee) atomicAdd(&g_deg[__ldg(&ei[Ee + e])], 1);
}

// ---------------- 3. scan ----------------
__global__ void k_scanA(){
    __shared__ int wsum[8], wexc[8];
    int t = threadIdx.x, blk = blockIdx.x;
    int base = blk*1024 + t*4;
    int v0 = (base+0<Nn)?g_deg[base+0]:0;
    int v1 = (base+1<Nn)?g_deg[base+1]:0;
    int v2 = (base+2<Nn)?g_deg[base+2]:0;
    int v3 = (base+3<Nn)?g_deg[base+3]:0;
    int s = v0+v1+v2+v3;
    int lane = t&31, w = t>>5;
    int ps = s;
#pragma unroll
    for(int off=1; off<32; off<<=1){
        int n = __shfl_up_sync(0xffffffffu, ps, off);
        if(lane>=off) ps += n;
    }
    if(lane==31) wsum[w] = ps;
    __syncthreads();
    if(t==0){
        int r=0;
#pragma unroll
        for(int k=0;k<8;k++){ wexc[k]=r; r+=wsum[k]; }
        g_bsum[blk]=r;
    }
    __syncthreads();
    int run = wexc[w] + ps - s;
    if(base+0<Nn) g_off[base+0]=run; run+=v0;
    if(base+1<Nn) g_off[base+1]=run; run+=v1;
    if(base+2<Nn) g_off[base+2]=run; run+=v2;
    if(base+3<Nn) g_off[base+3]=run;
}
__global__ void k_scanB(){
    if(threadIdx.x==0){
        int r=0;
        for(int b=0;b<NBLK;b++){ g_boff[b]=r; r+=g_bsum[b]; }
        g_off[Nn]=EPt;
    }
}
__global__ void k_scanC(){
    int blk = blockIdx.x;
    if(blk==0) return;
    int add = g_boff[blk];
    int base = blk*1024 + threadIdx.x*4;
#pragma unroll
    for(int j=0;j<4;j++)
        if(base+j < Nn) g_off[base+j] += add;
}

// ---------------- 4. scatter: dots from ea + sum_ea; slot 0 reserved ----------------
__global__ __launch_bounds__(256) void k_scatter(const int* __restrict__ ei,
                                                 const float* __restrict__ ea){
    __shared__ float sv1[64], sv2[16], ssum[16];
    int t = threadIdx.x;
    if(t < 64) sv1[t] = g_v1[t];
    if(t < 16){ sv2[t] = g_v2[t]; ssum[t] = 0.f; }
    __syncthreads();
    int e = blockIdx.x*blockDim.x + t;
    float r[16];
#pragma unroll
    for(int i=0;i<16;i++) r[i]=0.f;
    if(e < Ee){
        int s = __ldg(&ei[e]), d = __ldg(&ei[Ee + e]);
        const float4* rp = (const float4*)(ea + (size_t)e*16);
        ((float4*)r)[0]=__ldg(rp);   ((float4*)r)[1]=__ldg(rp+1);
        ((float4*)r)[2]=__ldg(rp+2); ((float4*)r)[3]=__ldg(rp+3);
        float ae[4];
#pragma unroll
        for(int h=0;h<4;h++){
            float a=0.f;
#pragma unroll
            for(int i=0;i<16;i++) a += sv1[h*16+i]*r[i];
            ae[h]=a;
        }
        float a2=0.f;
#pragma unroll
        for(int i=0;i<16;i++) a2 += sv2[i]*r[i];
        int pos = g_off[d] + 1 + atomicAdd(&g_cur[d], 1);
        g_ssrc[pos] = s;
        *(float4*)&g_sae1[(size_t)pos*4] = make_float4(ae[0],ae[1],ae[2],ae[3]);
        g_sae2[pos] = a2;
    }
#pragma unroll
    for(int off=16; off; off>>=1)
#pragma unroll
        for(int i=0;i<16;i++) r[i] += __shfl_xor_sync(0xffffffffu, r[i], off);
    if((t & 31)==0)
#pragma unroll
        for(int i=0;i<16;i++) atomicAdd(&ssum[i], r[i]);
    __syncthreads();
    if(t < 16) atomicAdd(&g_sum_ea[t], ssum[t]);
}

// ---------------- 5. self-loop fill ----------------
__global__ void k_selfloop(){
    __shared__ float slae1[4];
    __shared__ float slae2;
    int t = threadIdx.x;
    if(t < 4){
        float s = 0.f;
        for(int d=0;d<16;d++) s += (g_sum_ea[d]*(1.0f/(float)Ee))*g_v1[t*16+d];
        slae1[t] = s;
    }
    if(t == 4){
        float s = 0.f;
        for(int d=0;d<16;d++) s += (g_sum_ea[d]*(1.0f/(float)Ee))*g_v2[d];
        slae2 = s;
    }
    __syncthreads();
    int d = blockIdx.x*blockDim.x + t;
    if(d >= Nn) return;
    int pos = g_off[d];
    g_ssrc[pos] = d;
    *(float4*)&g_sae1[(size_t)pos*4] = make_float4(slae1[0],slae1[1],slae1[2],slae1[3]);
    g_sae2[pos] = slae2;
}

// ---------------- 6. GEMM: 64xNC block, 128 threads, 8x(NC/16) register tile ----------------
template<int NC, bool ELU, typename TA>
__global__ __launch_bounds__(128) void k_gemm(const TA* __restrict__ A,
                                              const float* __restrict__ W,
                                              const float* __restrict__ abias,
                                              const float* __restrict__ atts,
                                              const float* __restrict__ attd,
                                              __half* __restrict__ C,
                                              float* __restrict__ oasrc,
                                              float* __restrict__ oadst, int M){
    constexpr int CPT = NC/16;
    constexpr int AST = 68;
    __shared__ float AsT[32*AST];
    __shared__ float Ws[32*NC];
    __shared__ float as_s[NC], ad_s[NC];
    const int t  = threadIdx.x;
    const int tr = t >> 4, tc = t & 15;
    const int r0 = blockIdx.x * 64;
    if(t < NC){ as_s[t]=__ldg(&atts[t]); ad_s[t]=__ldg(&attd[t]); }
    float acc[8][CPT];
#pragma unroll
    for(int i=0;i<8;i++)
#pragma unroll
        for(int j=0;j<CPT;j++) acc[i][j]=0.f;

    for(int kc=0; kc<128; kc+=32){
        if constexpr (!ELU){
#pragma unroll
            for(int i=0;i<4;i++){
                int idx = t + i*128; int r = idx>>3; int c4 = idx&7;
                float4 v = make_float4(0.f,0.f,0.f,0.f);
                if(r0 + r < M) v = __ldg((const float4*)&((const float*)A)[(size_t)(r0+r)*128 + kc + c4*4]);
                AsT[(c4*4+0)*AST + r] = v.x;
                AsT[(c4*4+1)*AST + r] = v.y;
                AsT[(c4*4+2)*AST + r] = v.z;
                AsT[(c4*4+3)*AST + r] = v.w;
            }
        } else {
#pragma unroll
            for(int i=0;i<2;i++){
                int idx = t + i*128; int r = idx>>2; int c8 = (idx&3)*8;
                float f[8] = {0,0,0,0,0,0,0,0};
                if(r0 + r < M){
                    uint4 u = __ldg((const uint4*)&((const __half*)A)[(size_t)(r0+r)*128 + kc + c8]);
                    float2 a0=__half22float2(*(__half2*)&u.x), a1=__half22float2(*(__half2*)&u.y);
                    float2 a2=__half22float2(*(__half2*)&u.z), a3=__half22float2(*(__half2*)&u.w);
                    f[0]=a0.x; f[1]=a0.y; f[2]=a1.x; f[3]=a1.y;
                    f[4]=a2.x; f[5]=a2.y; f[6]=a3.x; f[7]=a3.y;
                    float4 b0 = __ldg((const float4*)&abias[kc+c8]);
                    float4 b1 = __ldg((const float4*)&abias[kc+c8+4]);
                    f[0]+=b0.x; f[1]+=b0.y; f[2]+=b0.z; f[3]+=b0.w;
                    f[4]+=b1.x; f[5]+=b1.y; f[6]+=b1.z; f[7]+=b1.w;
#pragma unroll
                    for(int j=0;j<8;j++) f[j] = f[j]>0.f ? f[j] : expm1f(f[j]);
                }
#pragma unroll
                for(int j=0;j<8;j++) AsT[(c8+j)*AST + r] = f[j];
            }
        }
#pragma unroll
        for(int f=t; f < 32*NC/4; f += 128){
            int k = f/(NC/4); int c = f%(NC/4);
            *(float4*)&Ws[k*NC + c*4] = __ldg((const float4*)&W[(size_t)(kc+k)*NC + c*4]);
        }
        __syncthreads();
#pragma unroll 4
        for(int kk=0; kk<32; kk++){
            float4 a0 = *(const float4*)&AsT[kk*AST + tr*8];
            float4 a1 = *(const float4*)&AsT[kk*AST + tr*8 + 4];
            float av[8] = {a0.x,a0.y,a0.z,a0.w,a1.x,a1.y,a1.z,a1.w};
            float4 b0 = *(const float4*)&Ws[kk*NC + tc*CPT];
#pragma unroll
            for(int i=0;i<8;i++){
                acc[i][0]+=av[i]*b0.x; acc[i][1]+=av[i]*b0.y;
                acc[i][2]+=av[i]*b0.z; acc[i][3]+=av[i]*b0.w;
            }
            if constexpr (CPT == 8){
                float4 b1 = *(const float4*)&Ws[kk*NC + tc*CPT + 4];
#pragma unroll
                for(int i=0;i<8;i++){
                    acc[i][4]+=av[i]*b1.x; acc[i][5]+=av[i]*b1.y;
                    acc[i][6]+=av[i]*b1.z; acc[i][7]+=av[i]*b1.w;
                }
            }
        }
        __syncthreads();
    }
#pragma unroll
    for(int i=0;i<8;i++){
        int row = r0 + tr*8 + i;
        float ps=0.f, pd=0.f;
#pragma unroll
        for(int j=0;j<CPT;j++){
            float a = acc[i][j];
            ps += a*as_s[tc*CPT+j]; pd += a*ad_s[tc*CPT+j];
        }
        if constexpr (NC == 128){
            ps += __shfl_xor_sync(0xffffffffu, ps, 1); pd += __shfl_xor_sync(0xffffffffu, pd, 1);
            ps += __shfl_xor_sync(0xffffffffu, ps, 2); pd += __shfl_xor_sync(0xffffffffu, pd, 2);
            if((tc&3)==0 && row<M){ oasrc[row*4+(tc>>2)]=ps; oadst[row*4+(tc>>2)]=pd; }
        } else {
            ps += __shfl_xor_sync(0xffffffffu, ps, 1); pd += __shfl_xor_sync(0xffffffffu, pd, 1);
            ps += __shfl_xor_sync(0xffffffffu, ps, 2); pd += __shfl_xor_sync(0xffffffffu, pd, 2);
            ps += __shfl_xor_sync(0xffffffffu, ps, 4); pd += __shfl_xor_sync(0xffffffffu, pd, 4);
            ps += __shfl_xor_sync(0xffffffffu, ps, 8); pd += __shfl_xor_sync(0xffffffffu, pd, 8);
            if(tc==0 && row<M){ oasrc[row]=ps; oadst[row]=pd; }
        }
        if(row < M){
            __half2 hh[CPT/2];
#pragma unroll
            for(int j=0;j<CPT/2;j++)
                hh[j] = __float22half2_rn(make_float2(acc[i][2*j], acc[i][2*j+1]));
            if constexpr (CPT == 8)
                *(uint4*)&C[(size_t)row*NC + tc*CPT] = *(uint4*)hh;
            else
                *(uint2*)&C[(size_t)row*NC + tc*CPT] = *(uint2*)hh;
        }
    }
}

// ---------------- 7. fused layer-1: 2 nodes/warp, x8 unroll ----------------
#define COMB8(a, u) { \
    float2 fa=__half22float2(*(__half2*)&(u).x), fb=__half22float2(*(__half2*)&(u).y); \
    float2 fc=__half22float2(*(__half2*)&(u).z), fd=__half22float2(*(__half2*)&(u).w); \
    if((a) <= m){ float w_=__expf((a)-m); sden+=w_; \
        acc[0]+=fa.x*w_; acc[1]+=fa.y*w_; acc[2]+=fb.x*w_; acc[3]+=fb.y*w_; \
        acc[4]+=fc.x*w_; acc[5]+=fc.y*w_; acc[6]+=fd.x*w_; acc[7]+=fd.y*w_; } \
    else { float sc=__expf(m-(a)); sden=sden*sc+1.f; \
        acc[0]=acc[0]*sc+fa.x; acc[1]=acc[1]*sc+fa.y; acc[2]=acc[2]*sc+fb.x; acc[3]=acc[3]*sc+fb.y; \
        acc[4]=acc[4]*sc+fc.x; acc[5]=acc[5]*sc+fc.y; acc[6]=acc[6]*sc+fd.x; acc[7]=acc[7]*sc+fd.y; m=(a);} }

__global__ __launch_bounds__(256) void k_layer1(){
    int lane = threadIdx.x & 31;
    int warp = (blockIdx.x*blockDim.x + threadIdx.x) >> 5;
    int side = lane >> 4, sl = lane & 15;
    int d = warp*2 + side;
    if(d >= Nn) return;
    int beg = g_off[d], end = g_off[d+1];
    int h = sl >> 2;
    float adst = __ldg(&g_adst1[d*4+h]);
    float m = -1e30f, sden = 0.f;
    float acc[8] = {0.f,0.f,0.f,0.f,0.f,0.f,0.f,0.f};
    int i = beg;
    for(; i+8 <= end; i+=8){
        int s_[8];
#pragma unroll
        for(int u=0;u<8;u++) s_[u] = __ldg(&g_ssrc[i+u]);
        float a_[8];
#pragma unroll
        for(int u=0;u<8;u++)
            a_[u] = lrelu(__ldg(&g_asrc1[s_[u]*4+h]) + adst
                          + __ldg(&g_sae1[(size_t)(i+u)*4+h]));
        uint4 hv[8];
#pragma unroll
        for(int u=0;u<8;u++)
            hv[u] = __ldg((const uint4*)&g_h1[(size_t)s_[u]*128 + sl*8]);
#pragma unroll
        for(int u=0;u<8;u++){
            COMB8(a_[u], hv[u]);
        }
    }
    for(; i+4 <= end; i+=4){
        int s_[4];
#pragma unroll
        for(int u=0;u<4;u++) s_[u] = __ldg(&g_ssrc[i+u]);
        float a_[4];
#pragma unroll
        for(int u=0;u<4;u++)
            a_[u] = lrelu(__ldg(&g_asrc1[s_[u]*4+h]) + adst
                          + __ldg(&g_sae1[(size_t)(i+u)*4+h]));
        uint4 hv[4];
#pragma unroll
        for(int u=0;u<4;u++)
            hv[u] = __ldg((const uint4*)&g_h1[(size_t)s_[u]*128 + sl*8]);
#pragma unroll
        for(int u=0;u<4;u++){
            COMB8(a_[u], hv[u]);
        }
    }
    for(; i<end; i++){
        int s = __ldg(&g_ssrc[i]);
        float a = lrelu(__ldg(&g_asrc1[s*4+h])+adst+__ldg(&g_sae1[(size_t)i*4+h]));
        uint4 hv = __ldg((const uint4*)&g_h1[(size_t)s*128+sl*8]);
        COMB8(a,hv);
    }
    float inv = 1.f/sden;
    __half2 o[4];
#pragma unroll
    for(int j=0;j<4;j++)
        o[j] = __float22half2_rn(make_float2(acc[2*j]*inv, acc[2*j+1]*inv));
    *(uint4*)&g_out1[(size_t)d*128 + sl*8] = *(uint4*)o;
}

// ---------------- 8. fused layer-2 + pool: 2 nodes/warp, x8 unroll ----------------
#define COMB4(a, u) { \
    float2 fa=__half22float2(*(__half2*)&(u).x), fb=__half22float2(*(__half2*)&(u).y); \
    if((a) <= m){ float w_=__expf((a)-m); sden+=w_; \
        acc[0]+=fa.x*w_; acc[1]+=fa.y*w_; acc[2]+=fb.x*w_; acc[3]+=fb.y*w_; } \
    else { float sc=__expf(m-(a)); sden=sden*sc+1.f; \
        acc[0]=acc[0]*sc+fa.x; acc[1]=acc[1]*sc+fa.y; acc[2]=acc[2]*sc+fb.x; acc[3]=acc[3]*sc+fb.y; m=(a);} }

__global__ __launch_bounds__(256) void k_layer2(const int* __restrict__ batch){
    int lane = threadIdx.x & 31;
    int warp = (blockIdx.x*blockDim.x + threadIdx.x) >> 5;
    int side = lane >> 4, sl = lane & 15;
    int d = warp*2 + side;
    if(d >= Nn) return;
    int beg = g_off[d], end = g_off[d+1];
    float adst = __ldg(&g_adst2[d]);
    float m = -1e30f, sden = 0.f;
    float acc[4] = {0.f,0.f,0.f,0.f};
    int i = beg;
    for(; i+8 <= end; i+=8){
        int s_[8];
#pragma unroll
        for(int u=0;u<8;u++) s_[u] = __ldg(&g_ssrc[i+u]);
        float a_[8];
#pragma unroll
        for(int u=0;u<8;u++)
            a_[u] = lrelu(__ldg(&g_asrc2[s_[u]]) + adst + __ldg(&g_sae2[i+u]));
        uint2 hv[8];
#pragma unroll
        for(int u=0;u<8;u++)
            hv[u] = __ldg((const uint2*)&g_h2[(size_t)s_[u]*64 + sl*4]);
#pragma unroll
        for(int u=0;u<8;u++){
            COMB4(a_[u], hv[u]);
        }
    }
    for(; i+4 <= end; i+=4){
        int s_[4];
#pragma unroll
        for(int u=0;u<4;u++) s_[u] = __ldg(&g_ssrc[i+u]);
        float a_[4];
#pragma unroll
        for(int u=0;u<4;u++)
            a_[u] = lrelu(__ldg(&g_asrc2[s_[u]]) + adst + __ldg(&g_sae2[i+u]));
        uint2 hv[4];
#pragma unroll
        for(int u=0;u<4;u++)
            hv[u] = __ldg((const uint2*)&g_h2[(size_t)s_[u]*64 + sl*4]);
#pragma unroll
        for(int u=0;u<4;u++){
            COMB4(a_[u], hv[u]);
        }
    }
    for(; i<end; i++){
        int s = __ldg(&g_ssrc[i]);
        float a = lrelu(__ldg(&g_asrc2[s])+adst+__ldg(&g_sae2[i]));
        uint2 hv = __ldg((const uint2*)&g_h2[(size_t)s*64+sl*4]);
        COMB4(a,hv);
    }
    float inv = 1.f/sden;
    int g = __ldg(&batch[d]);
    atomicAdd((float4*)&g_pool[g*64 + sl*4],
              make_float4(acc[0]*inv, acc[1]*inv, acc[2]*inv, acc[3]*inv));
    if(sl==0) atomicAdd(&g_cnt[g], 1);
}

// ---------------- 9. final ----------------
__global__ void k_final(float* __restrict__ out, const float* __restrict__ b2){
    int i = blockIdx.x*blockDim.x + threadIdx.x;
    if(i >= Gg*64) return;
    out[i] = g_pool[i] / fmaxf((float)g_cnt[i >> 6], 1.0f) + __ldg(&b2[i & 63]);
}

// ---------------- host launcher ----------------
extern "C" void kernel_launch(void* const* d_in, const int* in_sizes, int n_in,
                              void* d_out, int out_size){
    (void)in_sizes; (void)n_in; (void)out_size;
    const float* x     = (const float*)d_in[0];
    const int*   ei    = (const int*)d_in[1];
    const float* ea    = (const float*)d_in[2];
    const int*   batch = (const int*)d_in[3];
    const float* W1    = (const float*)d_in[4];
    const float* as1   = (const float*)d_in[5];
    const float* ad1   = (const float*)d_in[6];
    const float* We1   = (const float*)d_in[7];
    const float* ae1   = (const float*)d_in[8];
    const float* b1    = (const float*)d_in[9];
    const float* W2    = (const float*)d_in[10];
    const float* as2   = (const float*)d_in[11];
    const float* ad2   = (const float*)d_in[12];
    const float* We2   = (const float*)d_in[13];
    const float* ae2   = (const float*)d_in[14];
    const float* b2    = (const float*)d_in[15];
    float*       out   = (float*)d_out;

    void *p_h1,*p_out1,*p_h2,*p_asrc1,*p_adst1,*p_asrc2,*p_adst2;
    cudaGetSymbolAddress(&p_h1,   g_h1);
    cudaGetSymbolAddress(&p_out1, g_out1);
    cudaGetSymbolAddress(&p_h2,   g_h2);
    cudaGetSymbolAddress(&p_asrc1, g_asrc1);
    cudaGetSymbolAddress(&p_adst1, g_adst1);
    cudaGetSymbolAddress(&p_asrc2, g_asrc2);
    cudaGetSymbolAddress(&p_adst2, g_adst2);

    cudaStream_t s2;
    cudaEvent_t evFork, evJoin;
    cudaStreamCreateWithFlags(&s2, cudaStreamNonBlocking);
    cudaEventCreateWithFlags(&evFork, cudaEventDisableTiming);
    cudaEventCreateWithFlags(&evJoin, cudaEventDisableTiming);

    cudaEventRecord(evFork, 0);

    k_init<<<(Nn+255)/256, 256>>>(We1, ae1, We2, ae2);   // #1
    k_hist<<<(Ee+255)/256, 256>>>(ei);                   // #2
    k_scanA<<<NBLK, 256>>>();                            // #3

    cudaStreamWaitEvent(s2, evFork, 0);
    k_gemm<128,false,float><<<(Nn+63)/64, 128, 0, s2>>>(x, W1, nullptr, as1, ad1,
                        (__half*)p_h1, (float*)p_asrc1, (float*)p_adst1, Nn);  // #4 (ncu target)
    cudaEventRecord(evJoin, s2);

    k_scanB<<<1, 32>>>();                                // #5
    k_scanC<<<NBLK, 256>>>();                            // #6
    k_scatter<<<(Ee+255)/256, 256>>>(ei, ea);            // #7
    k_selfloop<<<(Nn+255)/256, 256>>>();                 // #8

    cudaStreamWaitEvent(0, evJoin, 0);
    k_layer1<<<(Nn/2*32+255)/256, 256>>>();              // #9

    k_gemm<64,true,__half><<<(Nn+63)/64, 128>>>((const __half*)p_out1, W2, b1, as2, ad2,
                        (__half*)p_h2, (float*)p_asrc2, (float*)p_adst2, Nn);  // #10
    k_layer2<<<(Nn/2*32+255)/256, 256>>>(batch);         // #11

    k_final<<<(Gg*64+255)/256, 256>>>(out, b2);          // #12
}